// round 2
// baseline (speedup 1.0000x reference)
#include <cuda_runtime.h>
#include <cuda_bf16.h>

// MotionPrimitiveDecoder: logits[b,n,t,a] = dot(df[b,n,t,a,:], z[b,n,:]) + cd[t,a] - mean_fa(cd[t,:])
// where cd = ctx_features . u_ctx_w.  The frenet/polyline projection term is constant
// across (t,a) for fixed (b,n) and cancels exactly in the u - u_mean centering, so
// map_polylines / idx / pts are never read.
//
// Shapes: B=32, N=64, T=40, A=6, Z=64, C=3.

#define B_DIM 32
#define N_DIM 64
#define T_DIM 40
#define A_DIM 6
#define Z_DIM 64
#define TA_DIM (T_DIM * A_DIM)   // 240

__global__ __launch_bounds__(256, 4) void mpd_kernel(
    const float* __restrict__ z,     // [B,N,Z]
    const float* __restrict__ df,    // [B,N,T,A,Z]
    const float* __restrict__ ctx,   // [B,N,T,A,3]
    const int*   __restrict__ fa,    // [B,N,T,A]
    const float* __restrict__ w,     // [3]
    float* __restrict__ out)         // [B,N,T,A]
{
    __shared__ float z_s[Z_DIM];
    __shared__ float cd_s[TA_DIM];
    __shared__ float mean_s[T_DIM];

    const int bn  = blockIdx.x;           // 0 .. B*N-1
    const int tid = threadIdx.x;

    const long zb  = (long)bn * Z_DIM;
    const long dfb = (long)bn * TA_DIM * Z_DIM;
    const long cb  = (long)bn * TA_DIM * 3;
    const long fb  = (long)bn * TA_DIM;

    // z into smem
    if (tid < Z_DIM) z_s[tid] = z[zb + tid];

    const float w0 = __ldg(w), w1 = __ldg(w + 1), w2 = __ldg(w + 2);

    // cd[ta] = ctx[ta,:] . w   (240 contiguous-ish reads, 720 floats total)
    if (tid < TA_DIM) {
        const float* c = ctx + cb + (long)tid * 3;
        cd_s[tid] = c[0] * w0 + c[1] * w1 + c[2] * w2;
    }
    __syncthreads();

    // feasibility-masked mean per t
    if (tid < T_DIM) {
        const int* f = fa + fb + tid * A_DIM;
        float s_all = 0.f, s_f = 0.f;
        int cnt = 0;
        #pragma unroll
        for (int a = 0; a < A_DIM; a++) {
            float cdv = cd_s[tid * A_DIM + a];
            s_all += cdv;
            if (f[a]) { s_f += cdv; cnt++; }
        }
        mean_s[tid] = cnt ? (s_f / (float)cnt) : (s_all / (float)A_DIM);
    }
    __syncthreads();

    // main streaming phase: df dot z, one warp computes 2 (t,a) outputs per iter
    const int warp = tid >> 5;
    const int lane = tid & 31;

    const float zx = z_s[2 * lane];
    const float zy = z_s[2 * lane + 1];
    const float2* dfp = (const float2*)(df + dfb);

    #pragma unroll
    for (int i = 0; i < 15; i++) {
        const int ta0 = warp * 2 + i * 16;
        const int ta1 = ta0 + 1;

        float2 v0 = dfp[(long)ta0 * 32 + lane];   // 256B coalesced per warp
        float2 v1 = dfp[(long)ta1 * 32 + lane];

        float p0 = v0.x * zx + v0.y * zy;
        float p1 = v1.x * zx + v1.y * zy;

        #pragma unroll
        for (int o = 16; o > 0; o >>= 1) {
            p0 += __shfl_xor_sync(0xFFFFFFFFu, p0, o);
            p1 += __shfl_xor_sync(0xFFFFFFFFu, p1, o);
        }

        if (lane == 0) {
            out[fb + ta0] = p0 + cd_s[ta0] - mean_s[ta0 / A_DIM];
            out[fb + ta1] = p1 + cd_s[ta1] - mean_s[ta1 / A_DIM];
        }
    }
}

extern "C" void kernel_launch(void* const* d_in, const int* in_sizes, int n_in,
                              void* d_out, int out_size) {
    // metadata order: map_polylines, idx, pts, z, decision_features,
    //                 ctx_features, feasible_actions, u_ctx_w, u_ctx_b
    const float* z   = (const float*)d_in[3];
    const float* df  = (const float*)d_in[4];
    const float* ctx = (const float*)d_in[5];
    const int*   fa  = (const int*)d_in[6];
    const float* w   = (const float*)d_in[7];
    float* out = (float*)d_out;

    mpd_kernel<<<B_DIM * N_DIM, 256>>>(z, df, ctx, fa, w, out);
}

// round 3
// speedup vs baseline: 1.1293x; 1.1293x over previous
#include <cuda_runtime.h>
#include <cuda_bf16.h>

// MotionPrimitiveDecoder: logits[b,n,t,a] = dot(df[b,n,t,a,:], z[b,n,:]) + cd[t,a] - mean_fa(cd[t,:])
// where cd = ctx_features . u_ctx_w.  The frenet/polyline projection term is constant
// across (t,a) for fixed (b,n) and cancels exactly in the u - u_mean centering, so
// map_polylines / idx / pts are never read.
//
// Shapes: B=32, N=64, T=40, A=6, Z=64, C=3.
//
// R3: float4 loads, half-warp-per-row reduction (4 shuffles for 2 rows),
//     5 loads in flight per warp per batch (MLP=5).

#define B_DIM 32
#define N_DIM 64
#define T_DIM 40
#define A_DIM 6
#define Z_DIM 64
#define TA_DIM (T_DIM * A_DIM)   // 240

__global__ __launch_bounds__(256) void mpd_kernel(
    const float* __restrict__ z,     // [B,N,Z]
    const float* __restrict__ df,    // [B,N,T,A,Z]
    const float* __restrict__ ctx,   // [B,N,T,A,3]
    const int*   __restrict__ fa,    // [B,N,T,A]
    const float* __restrict__ w,     // [3]
    float* __restrict__ out)         // [B,N,T,A]
{
    __shared__ float4 z4_s[Z_DIM / 4];       // 16 float4 = 64 floats
    __shared__ float  cd_s[TA_DIM];
    __shared__ float  mean_s[T_DIM];

    const int bn  = blockIdx.x;              // 0 .. B*N-1
    const int tid = threadIdx.x;

    const long zb  = (long)bn * Z_DIM;
    const long dfb = (long)bn * TA_DIM * Z_DIM;
    const long cb  = (long)bn * TA_DIM * 3;
    const long fb  = (long)bn * TA_DIM;

    // z into smem (16 float4 = 256B, row is 256B-aligned)
    if (tid < Z_DIM / 4) z4_s[tid] = ((const float4*)(z + zb))[tid];

    const float w0 = __ldg(w), w1 = __ldg(w + 1), w2 = __ldg(w + 2);

    // cd[ta] = ctx[ta,:] . w
    if (tid < TA_DIM) {
        const float* c = ctx + cb + (long)tid * 3;
        cd_s[tid] = c[0] * w0 + c[1] * w1 + c[2] * w2;
    }
    __syncthreads();

    // feasibility-masked mean per t
    if (tid < T_DIM) {
        const int* f = fa + fb + tid * A_DIM;
        float s_all = 0.f, s_f = 0.f;
        int cnt = 0;
        #pragma unroll
        for (int a = 0; a < A_DIM; a++) {
            float cdv = cd_s[tid * A_DIM + a];
            s_all += cdv;
            if (f[a]) { s_f += cdv; cnt++; }
        }
        mean_s[tid] = cnt ? (s_f / (float)cnt) : (s_all / (float)A_DIM);
    }
    __syncthreads();

    // streaming phase: 8 warps, each warp covers 2 rows per slot (half-warp per row),
    // 15 slots per warp, batched 5 loads in flight.
    const int warp = tid >> 5;
    const int lane = tid & 31;
    const int half = lane >> 4;              // which row within the warp's pair
    const int hl   = lane & 15;              // float4 index within the row

    const float4 zv = z4_s[hl];
    const float4* dfp = (const float4*)(df + dfb);

    #pragma unroll
    for (int batch = 0; batch < 3; batch++) {
        float4 v[5];
        int ta[5];
        #pragma unroll
        for (int j = 0; j < 5; j++) {
            const int slot = batch * 5 + j;
            ta[j] = slot * 16 + warp * 2 + half;          // unique row in [0,240)
            v[j] = dfp[(long)ta[j] * 16 + hl];            // 256B per half-warp, coalesced
        }
        #pragma unroll
        for (int j = 0; j < 5; j++) {
            float p = v[j].x * zv.x + v[j].y * zv.y + v[j].z * zv.z + v[j].w * zv.w;
            p += __shfl_xor_sync(0xFFFFFFFFu, p, 1);
            p += __shfl_xor_sync(0xFFFFFFFFu, p, 2);
            p += __shfl_xor_sync(0xFFFFFFFFu, p, 4);
            p += __shfl_xor_sync(0xFFFFFFFFu, p, 8);
            if (hl == 0) {
                out[fb + ta[j]] = p + cd_s[ta[j]] - mean_s[ta[j] / A_DIM];
            }
        }
    }
}

extern "C" void kernel_launch(void* const* d_in, const int* in_sizes, int n_in,
                              void* d_out, int out_size) {
    // metadata order: map_polylines, idx, pts, z, decision_features,
    //                 ctx_features, feasible_actions, u_ctx_w, u_ctx_b
    const float* z   = (const float*)d_in[3];
    const float* df  = (const float*)d_in[4];
    const float* ctx = (const float*)d_in[5];
    const int*   fa  = (const int*)d_in[6];
    const float* w   = (const float*)d_in[7];
    float* out = (float*)d_out;

    mpd_kernel<<<B_DIM * N_DIM, 256>>>(z, df, ctx, fa, w, out);
}

// round 5
// speedup vs baseline: 1.2252x; 1.0849x over previous
#include <cuda_runtime.h>
#include <cuda_bf16.h>

// MotionPrimitiveDecoder: logits[b,n,t,a] = dot(df[b,n,t,a,:], z[b,n,:]) + cd[t,a] - mean_fa(cd[t,:])
// where cd = ctx_features . u_ctx_w.  The frenet/polyline projection term is constant
// across (t,a) for fixed (b,n) and cancels exactly in the u - u_mean centering, so
// map_polylines / idx / pts are never read.
//
// Shapes: B=32, N=64, T=40, A=6, Z=64, C=3.
//
// R4: df prefetch issued BEFORE the prologue (prologue hides in load shadow),
//     rolling 5-deep pipeline (no batch-drain bubbles).

#define B_DIM 32
#define N_DIM 64
#define T_DIM 40
#define A_DIM 6
#define Z_DIM 64
#define TA_DIM (T_DIM * A_DIM)   // 240

__global__ __launch_bounds__(256) void mpd_kernel(
    const float* __restrict__ z,     // [B,N,Z]
    const float* __restrict__ df,    // [B,N,T,A,Z]
    const float* __restrict__ ctx,   // [B,N,T,A,3]
    const int*   __restrict__ fa,    // [B,N,T,A]
    const float* __restrict__ w,     // [3]
    float* __restrict__ out)         // [B,N,T,A]
{
    __shared__ float4 z4_s[Z_DIM / 4];       // 16 float4 = 64 floats
    __shared__ float  cd_s[TA_DIM];
    __shared__ float  mean_s[T_DIM];

    const int bn  = blockIdx.x;              // 0 .. B*N-1
    const int tid = threadIdx.x;

    const long zb  = (long)bn * Z_DIM;
    const long dfb = (long)bn * TA_DIM * Z_DIM;
    const long cb  = (long)bn * TA_DIM * 3;
    const long fb  = (long)bn * TA_DIM;

    const int warp = tid >> 5;
    const int lane = tid & 31;
    const int half = lane >> 4;              // which row within the warp's pair
    const int hl   = lane & 15;              // float4 index within the row

    const float4* dfp = (const float4*)(df + dfb);

    // ---- prefetch first 5 streaming loads BEFORE anything else: the whole
    //      prologue below runs in their shadow, DRAM busy from cycle 0 ----
    float4 v[5];
    #pragma unroll
    for (int j = 0; j < 5; j++) {
        const int ta = j * 16 + warp * 2 + half;
        v[j] = dfp[(long)ta * 16 + hl];      // 256B per half-warp, coalesced
    }

    // ---- prologue ----
    if (tid < Z_DIM / 4) z4_s[tid] = ((const float4*)(z + zb))[tid];

    const float w0 = __ldg(w), w1 = __ldg(w + 1), w2 = __ldg(w + 2);

    float cdv = 0.f;
    if (tid < TA_DIM) {
        const float* c = ctx + cb + (long)tid * 3;
        cdv = c[0] * w0 + c[1] * w1 + c[2] * w2;
        cd_s[tid] = cdv;
    }
    __syncthreads();

    if (tid < T_DIM) {
        const int* f = fa + fb + tid * A_DIM;
        float s_all = 0.f, s_f = 0.f;
        int cnt = 0;
        #pragma unroll
        for (int a = 0; a < A_DIM; a++) {
            float cda = cd_s[tid * A_DIM + a];
            s_all += cda;
            if (f[a]) { s_f += cda; cnt++; }
        }
        mean_s[tid] = cnt ? (s_f / (float)cnt) : (s_all / (float)A_DIM);
    }
    __syncthreads();

    const float4 zv = z4_s[hl];

    // ---- rolling pipeline: reduce slot j, immediately refill with row j+5.
    //      Constant 5 loads in flight, no batch-boundary drain. ----
    #pragma unroll
    for (int j = 0; j < 15; j++) {
        const int ta = j * 16 + warp * 2 + half;
        const float4 x = v[j % 5];

        if (j + 5 < 15) {
            const int tan = (j + 5) * 16 + warp * 2 + half;
            v[j % 5] = dfp[(long)tan * 16 + hl];
        }

        float p = x.x * zv.x + x.y * zv.y + x.z * zv.z + x.w * zv.w;
        p += __shfl_xor_sync(0xFFFFFFFFu, p, 1);
        p += __shfl_xor_sync(0xFFFFFFFFu, p, 2);
        p += __shfl_xor_sync(0xFFFFFFFFu, p, 4);
        p += __shfl_xor_sync(0xFFFFFFFFu, p, 8);

        if (hl == 0) {
            out[fb + ta] = p + cd_s[ta] - mean_s[ta / A_DIM];
        }
    }
}

extern "C" void kernel_launch(void* const* d_in, const int* in_sizes, int n_in,
                              void* d_out, int out_size) {
    // metadata order: map_polylines, idx, pts, z, decision_features,
    //                 ctx_features, feasible_actions, u_ctx_w, u_ctx_b
    const float* z   = (const float*)d_in[3];
    const float* df  = (const float*)d_in[4];
    const float* ctx = (const float*)d_in[5];
    const int*   fa  = (const int*)d_in[6];
    const float* w   = (const float*)d_in[7];
    float* out = (float*)d_out;

    mpd_kernel<<<B_DIM * N_DIM, 256>>>(z, df, ctx, fa, w, out);
}